// round 15
// baseline (speedup 1.0000x reference)
#include <cuda_runtime.h>
#include <cuda_bf16.h>

// Problem constants
#define N_TOK 4096     // H*W
#define DH    64       // dim_head
#define NH    8        // heads
#define NB    2        // batch
#define CIN   256      // channels
#define INNER 512      // heads*dim_head
#define OQKV  1536     // 3*INNER

// Scratch: Q/K/V/O in [b*h][n][d] layout (fp32)
__device__ float g_q[(size_t)NB * NH * N_TOK * DH];
__device__ float g_k[(size_t)NB * NH * N_TOK * DH];
__device__ float g_v[(size_t)NB * NH * N_TOK * DH];
__device__ float g_o[(size_t)NB * NH * N_TOK * DH];

// ---------------------------------------------------------------------------
// Kernel 1: QKV projection.  qkv[b,o,n] = sum_c w_qkv[o,c] * x[b,c,n]
// Tile 64(o) x 64(n), K-chunks of 16, 4x4 register tiles.
// Writes directly into g_q/g_k/g_v at [b*NH+h][n][d]; Q pre-scaled by 1/8.
// Thread map: tx (0..15) -> o (so d is contiguous across tx -> coalesced
// float4 stores into the [n][d] layout), ty (0..15) -> n.
// ---------------------------------------------------------------------------
__global__ __launch_bounds__(256) void qkv_kernel(const float* __restrict__ x,
                                                  const float* __restrict__ w) {
    __shared__ float As[16 * 65];   // [k][o] transposed, padded
    __shared__ float Bs[16 * 64];   // [k][n]

    const int b  = blockIdx.z;
    const int o0 = blockIdx.x * 64;
    const int n0 = blockIdx.y * 64;
    const int tid = threadIdx.x;
    const int tx = tid & 15, ty = tid >> 4;

    const float* xb = x + (size_t)b * CIN * N_TOK;

    float acc[4][4];
#pragma unroll
    for (int i = 0; i < 4; i++)
#pragma unroll
        for (int j = 0; j < 4; j++) acc[i][j] = 0.f;

    for (int k0 = 0; k0 < CIN; k0 += 16) {
        // Load W tile [64 o][16 k] -> As[k][o]
        {
            const int r = tid >> 2;            // o in tile (0..63)
            const int c4 = (tid & 3) * 4;      // k in chunk
            float4 wv = *(const float4*)(w + (size_t)(o0 + r) * CIN + k0 + c4);
            As[(c4 + 0) * 65 + r] = wv.x;
            As[(c4 + 1) * 65 + r] = wv.y;
            As[(c4 + 2) * 65 + r] = wv.z;
            As[(c4 + 3) * 65 + r] = wv.w;
        }
        // Load X tile [16 k][64 n] -> Bs[k][n]
        {
            const int r = tid >> 4;            // k in chunk (0..15)
            const int n4 = (tid & 15) * 4;     // n in tile
            float4 xv = *(const float4*)(xb + (size_t)(k0 + r) * N_TOK + n0 + n4);
            *(float4*)&Bs[r * 64 + n4] = xv;
        }
        __syncthreads();

#pragma unroll
        for (int kk = 0; kk < 16; kk++) {
            float ra[4], rb[4];
#pragma unroll
            for (int i = 0; i < 4; i++) ra[i] = As[kk * 65 + tx * 4 + i];
#pragma unroll
            for (int j = 0; j < 4; j++) rb[j] = Bs[kk * 64 + ty * 4 + j];
#pragma unroll
            for (int i = 0; i < 4; i++)
#pragma unroll
                for (int j = 0; j < 4; j++) acc[i][j] += ra[i] * rb[j];
        }
        __syncthreads();
    }

    // Epilogue: decode o-tile -> (s, h); o tile never crosses a 64 boundary.
    const int s = o0 >> 9;           // 0=q, 1=k, 2=v
    const int h = (o0 >> 6) & 7;
    float* dst = (s == 0) ? g_q : ((s == 1) ? g_k : g_v);
    const float scale = (s == 0) ? 0.125f : 1.0f;   // 1/sqrt(64)
    const int bh = b * NH + h;
    const int d0 = tx * 4;

#pragma unroll
    for (int j = 0; j < 4; j++) {
        const int n = n0 + ty * 4 + j;
        float4 v = make_float4(acc[0][j] * scale, acc[1][j] * scale,
                               acc[2][j] * scale, acc[3][j] * scale);
        *(float4*)(dst + ((size_t)bh * N_TOK + n) * DH + d0) = v;
    }
}

// ---------------------------------------------------------------------------
// Kernel 2: flash attention (fp32, online softmax).
// One block per (q-tile of 64 rows, bh). Br=Bc=64, D=64. 256 threads (16x16):
//   S phase:  tx -> kv col, ty -> q row (4x4 per thread)
//   PV phase: tx -> d,      ty -> q row (4x4 per thread)
// Smem: Qs (unswizzled), KPs (K tile, later reused for P), Vs.
// K/V stored with XOR swizzle  elem[c][d] at c*64 + (d ^ (c&31)),
// P stored with                elem[r][c] at r*64 + (c ^ (r&31)).
// Exactly 48KB static shared.
// ---------------------------------------------------------------------------
__global__ __launch_bounds__(256) void attn_kernel() {
    __shared__ float Qs[64 * 64];
    __shared__ float KPs[64 * 64];
    __shared__ float Vs[64 * 64];

    const int bh = blockIdx.y;
    const int r0 = blockIdx.x * 64;
    const int tid = threadIdx.x;
    const int tx = tid & 15, ty = tid >> 4;

    const float* qb = g_q + (size_t)bh * N_TOK * DH;
    const float* kb = g_k + (size_t)bh * N_TOK * DH;
    const float* vb = g_v + (size_t)bh * N_TOK * DH;

    // Load Q tile (already scaled by 1/8)
#pragma unroll
    for (int p = 0; p < 4; p++) {
        const int row = p * 16 + (tid >> 4);
        const int c4 = (tid & 15) * 4;
        *(float4*)&Qs[row * 64 + c4] =
            *(const float4*)(qb + (size_t)(r0 + row) * DH + c4);
    }

    float m[4], l[4], Oa[4][4];
#pragma unroll
    for (int i = 0; i < 4; i++) {
        m[i] = -1e30f;
        l[i] = 0.f;
#pragma unroll
        for (int j = 0; j < 4; j++) Oa[i][j] = 0.f;
    }

    for (int t = 0; t < N_TOK / 64; t++) {
        __syncthreads();  // prev PV done (and Qs visible on t==0)

        // Load K & V tiles with swizzle
#pragma unroll
        for (int p = 0; p < 4; p++) {
            const int c = p * 16 + (tid >> 4);
            const int dq = (tid & 15) * 4;
            const int sw = c & 31;
            const size_t gofs = (size_t)(t * 64 + c) * DH + dq;
            float4 kv = *(const float4*)(kb + gofs);
            KPs[c * 64 + ((dq + 0) ^ sw)] = kv.x;
            KPs[c * 64 + ((dq + 1) ^ sw)] = kv.y;
            KPs[c * 64 + ((dq + 2) ^ sw)] = kv.z;
            KPs[c * 64 + ((dq + 3) ^ sw)] = kv.w;
            float4 vv = *(const float4*)(vb + gofs);
            Vs[c * 64 + ((dq + 0) ^ sw)] = vv.x;
            Vs[c * 64 + ((dq + 1) ^ sw)] = vv.y;
            Vs[c * 64 + ((dq + 2) ^ sw)] = vv.z;
            Vs[c * 64 + ((dq + 3) ^ sw)] = vv.w;
        }
        __syncthreads();

        // S = Q @ K^T  (scale already folded into Q)
        float acc[4][4];
#pragma unroll
        for (int i = 0; i < 4; i++)
#pragma unroll
            for (int j = 0; j < 4; j++) acc[i][j] = 0.f;

        int cbase[4], cswz[4];
#pragma unroll
        for (int j = 0; j < 4; j++) {
            const int c = tx * 4 + j;
            cbase[j] = c * 64;
            cswz[j] = c & 31;
        }
#pragma unroll 8
        for (int d = 0; d < 64; d++) {
            float rq[4], rk[4];
#pragma unroll
            for (int i = 0; i < 4; i++) rq[i] = Qs[(ty * 4 + i) * 64 + d];
#pragma unroll
            for (int j = 0; j < 4; j++) rk[j] = KPs[cbase[j] + (d ^ cswz[j])];
#pragma unroll
            for (int i = 0; i < 4; i++)
#pragma unroll
                for (int j = 0; j < 4; j++) acc[i][j] += rq[i] * rk[j];
        }

        // Online softmax (rows live in 16-lane groups: lanes sharing ty)
#pragma unroll
        for (int i = 0; i < 4; i++) {
            float mt = acc[i][0];
#pragma unroll
            for (int j = 1; j < 4; j++) mt = fmaxf(mt, acc[i][j]);
#pragma unroll
            for (int off = 1; off < 16; off <<= 1)
                mt = fmaxf(mt, __shfl_xor_sync(0xffffffffu, mt, off));
            const float mnew = fmaxf(m[i], mt);
            const float alpha = __expf(m[i] - mnew);
            float rs = 0.f;
#pragma unroll
            for (int j = 0; j < 4; j++) {
                const float pv = __expf(acc[i][j] - mnew);
                acc[i][j] = pv;
                rs += pv;
            }
#pragma unroll
            for (int off = 1; off < 16; off <<= 1)
                rs += __shfl_xor_sync(0xffffffffu, rs, off);
            l[i] = l[i] * alpha + rs;
            m[i] = mnew;
#pragma unroll
            for (int j = 0; j < 4; j++) Oa[i][j] *= alpha;
        }

        __syncthreads();  // everyone done reading K before overwriting with P
        // Stage P into KPs: P[r][c] at r*64 + (c ^ (r&31))
#pragma unroll
        for (int i = 0; i < 4; i++) {
            const int r = ty * 4 + i;
            const int rsw = r & 31;
#pragma unroll
            for (int j = 0; j < 4; j++)
                KPs[r * 64 + ((tx * 4 + j) ^ rsw)] = acc[i][j];
        }
        __syncthreads();

        // O += P @ V   (tx now indexes d)
#pragma unroll 8
        for (int c = 0; c < 64; c++) {
            float rp[4], rv[4];
            const int csw = c & 31;
#pragma unroll
            for (int i = 0; i < 4; i++) {
                const int r = ty * 4 + i;
                rp[i] = KPs[r * 64 + (c ^ (r & 31))];
            }
#pragma unroll
            for (int j = 0; j < 4; j++) rv[j] = Vs[c * 64 + ((tx * 4 + j) ^ csw)];
#pragma unroll
            for (int i = 0; i < 4; i++)
#pragma unroll
                for (int j = 0; j < 4; j++) Oa[i][j] += rp[i] * rv[j];
        }
    }

    // Normalize and write O[bh][n][d]
#pragma unroll
    for (int i = 0; i < 4; i++) {
        const float inv = 1.0f / l[i];
        float4 v = make_float4(Oa[i][0] * inv, Oa[i][1] * inv,
                               Oa[i][2] * inv, Oa[i][3] * inv);
        *(float4*)(g_o + ((size_t)bh * N_TOK + r0 + ty * 4 + i) * DH + tx * 4) = v;
    }
}

// ---------------------------------------------------------------------------
// Kernel 3: output projection + bias.
// out[b,c,n] = sum_i w_out[c,i] * O[b, i=(h*64+d), n] + b_out[c]
// where O is stored [bh][n][d]. Tile 64(c) x 64(n), K-chunks of 16
// (a 16-chunk never crosses an h boundary since 64 % 16 == 0).
// Thread map: tx -> n (coalesced stores), ty -> c.
// ---------------------------------------------------------------------------
__global__ __launch_bounds__(256) void outproj_kernel(const float* __restrict__ w,
                                                      const float* __restrict__ bias,
                                                      float* __restrict__ out) {
    __shared__ float As[16 * 65];    // [k][c] transposed, padded
    __shared__ float Bsn[64 * 17];   // [n][k], padded

    const int b  = blockIdx.z;
    const int c0 = blockIdx.x * 64;
    const int n0 = blockIdx.y * 64;
    const int tid = threadIdx.x;
    const int tx = tid & 15, ty = tid >> 4;

    const float* ob = g_o + (size_t)b * NH * N_TOK * DH;

    float acc[4][4];
#pragma unroll
    for (int i = 0; i < 4; i++)
#pragma unroll
        for (int j = 0; j < 4; j++) acc[i][j] = 0.f;

    for (int k0 = 0; k0 < INNER; k0 += 16) {
        const int h = k0 >> 6;
        const int dbase = k0 & 63;
        // W tile [64 c][16 k] -> As[k][c]
        {
            const int r = tid >> 2;
            const int c4 = (tid & 3) * 4;
            float4 wv = *(const float4*)(w + (size_t)(c0 + r) * INNER + k0 + c4);
            As[(c4 + 0) * 65 + r] = wv.x;
            As[(c4 + 1) * 65 + r] = wv.y;
            As[(c4 + 2) * 65 + r] = wv.z;
            As[(c4 + 3) * 65 + r] = wv.w;
        }
        // O tile: rows k (= d within head h), cols n; load float4 along d.
        {
            const int nidx = tid >> 2;         // 0..63
            const int kq = (tid & 3) * 4;      // 0..12
            float4 ov = *(const float4*)(ob + ((size_t)h * N_TOK + n0 + nidx) * DH +
                                         dbase + kq);
            Bsn[nidx * 17 + kq + 0] = ov.x;
            Bsn[nidx * 17 + kq + 1] = ov.y;
            Bsn[nidx * 17 + kq + 2] = ov.z;
            Bsn[nidx * 17 + kq + 3] = ov.w;
        }
        __syncthreads();

#pragma unroll
        for (int kk = 0; kk < 16; kk++) {
            float ra[4], rb[4];
#pragma unroll
            for (int i = 0; i < 4; i++) ra[i] = As[kk * 65 + ty * 4 + i];
#pragma unroll
            for (int j = 0; j < 4; j++) rb[j] = Bsn[(tx * 4 + j) * 17 + kk];
#pragma unroll
            for (int i = 0; i < 4; i++)
#pragma unroll
                for (int j = 0; j < 4; j++) acc[i][j] += ra[i] * rb[j];
        }
        __syncthreads();
    }

#pragma unroll
    for (int i = 0; i < 4; i++) {
        const int c = c0 + ty * 4 + i;
        const float bb = bias[c];
        float4 v = make_float4(acc[i][0] + bb, acc[i][1] + bb,
                               acc[i][2] + bb, acc[i][3] + bb);
        *(float4*)(out + ((size_t)b * CIN + c) * N_TOK + n0 + tx * 4) = v;
    }
}

// ---------------------------------------------------------------------------
// Launch: x, w_qkv, w_out, b_out (metadata order). Output fp32 [B,C,H,W].
// ---------------------------------------------------------------------------
extern "C" void kernel_launch(void* const* d_in, const int* in_sizes, int n_in,
                              void* d_out, int out_size) {
    const float* x     = (const float*)d_in[0];
    const float* w_qkv = (const float*)d_in[1];
    const float* w_out = (const float*)d_in[2];
    const float* b_out = (const float*)d_in[3];
    float* out = (float*)d_out;

    qkv_kernel<<<dim3(OQKV / 64, N_TOK / 64, NB), 256>>>(x, w_qkv);
    attn_kernel<<<dim3(N_TOK / 64, NB * NH), 256>>>();
    outproj_kernel<<<dim3(CIN / 64, N_TOK / 64, NB), 256>>>(w_out, b_out, out);
}

// round 16
// speedup vs baseline: 1.0005x; 1.0005x over previous
#include <cuda_runtime.h>
#include <cuda_bf16.h>

// Problem constants
#define N_TOK 4096     // H*W
#define DH    64       // dim_head
#define NH    8        // heads
#define NB    2        // batch
#define CIN   256      // channels
#define INNER 512      // heads*dim_head
#define OQKV  1536     // 3*INNER

// Scratch: Q/K/V/O in [b*h][n][d] layout (fp32)
__device__ float g_q[(size_t)NB * NH * N_TOK * DH];
__device__ float g_k[(size_t)NB * NH * N_TOK * DH];
__device__ float g_v[(size_t)NB * NH * N_TOK * DH];
__device__ float g_o[(size_t)NB * NH * N_TOK * DH];

// ---------------------------------------------------------------------------
// Kernel 1: QKV projection.  qkv[b,o,n] = sum_c w_qkv[o,c] * x[b,c,n]
// Tile 64(o) x 64(n), K-chunks of 16, 4x4 register tiles.
// Writes directly into g_q/g_k/g_v at [b*NH+h][n][d]; Q pre-scaled by 1/8.
// Thread map: tx (0..15) -> o (so d is contiguous across tx -> coalesced
// float4 stores into the [n][d] layout), ty (0..15) -> n.
// ---------------------------------------------------------------------------
__global__ __launch_bounds__(256) void qkv_kernel(const float* __restrict__ x,
                                                  const float* __restrict__ w) {
    __shared__ float As[16 * 65];   // [k][o] transposed, padded
    __shared__ float Bs[16 * 64];   // [k][n]

    const int b  = blockIdx.z;
    const int o0 = blockIdx.x * 64;
    const int n0 = blockIdx.y * 64;
    const int tid = threadIdx.x;
    const int tx = tid & 15, ty = tid >> 4;

    const float* xb = x + (size_t)b * CIN * N_TOK;

    float acc[4][4];
#pragma unroll
    for (int i = 0; i < 4; i++)
#pragma unroll
        for (int j = 0; j < 4; j++) acc[i][j] = 0.f;

    for (int k0 = 0; k0 < CIN; k0 += 16) {
        // Load W tile [64 o][16 k] -> As[k][o]
        {
            const int r = tid >> 2;            // o in tile (0..63)
            const int c4 = (tid & 3) * 4;      // k in chunk
            float4 wv = *(const float4*)(w + (size_t)(o0 + r) * CIN + k0 + c4);
            As[(c4 + 0) * 65 + r] = wv.x;
            As[(c4 + 1) * 65 + r] = wv.y;
            As[(c4 + 2) * 65 + r] = wv.z;
            As[(c4 + 3) * 65 + r] = wv.w;
        }
        // Load X tile [16 k][64 n] -> Bs[k][n]
        {
            const int r = tid >> 4;            // k in chunk (0..15)
            const int n4 = (tid & 15) * 4;     // n in tile
            float4 xv = *(const float4*)(xb + (size_t)(k0 + r) * N_TOK + n0 + n4);
            *(float4*)&Bs[r * 64 + n4] = xv;
        }
        __syncthreads();

#pragma unroll
        for (int kk = 0; kk < 16; kk++) {
            float ra[4], rb[4];
#pragma unroll
            for (int i = 0; i < 4; i++) ra[i] = As[kk * 65 + tx * 4 + i];
#pragma unroll
            for (int j = 0; j < 4; j++) rb[j] = Bs[kk * 64 + ty * 4 + j];
#pragma unroll
            for (int i = 0; i < 4; i++)
#pragma unroll
                for (int j = 0; j < 4; j++) acc[i][j] += ra[i] * rb[j];
        }
        __syncthreads();
    }

    // Epilogue: decode o-tile -> (s, h); o tile never crosses a 64 boundary.
    const int s = o0 >> 9;           // 0=q, 1=k, 2=v
    const int h = (o0 >> 6) & 7;
    float* dst = (s == 0) ? g_q : ((s == 1) ? g_k : g_v);
    const float scale = (s == 0) ? 0.125f : 1.0f;   // 1/sqrt(64)
    const int bh = b * NH + h;
    const int d0 = tx * 4;

#pragma unroll
    for (int j = 0; j < 4; j++) {
        const int n = n0 + ty * 4 + j;
        float4 v = make_float4(acc[0][j] * scale, acc[1][j] * scale,
                               acc[2][j] * scale, acc[3][j] * scale);
        *(float4*)(dst + ((size_t)bh * N_TOK + n) * DH + d0) = v;
    }
}

// ---------------------------------------------------------------------------
// Kernel 2: flash attention (fp32, online softmax).
// One block per (q-tile of 64 rows, bh). Br=Bc=64, D=64. 256 threads (16x16):
//   S phase:  tx -> kv col, ty -> q row (4x4 per thread)
//   PV phase: tx -> d,      ty -> q row (4x4 per thread)
// Smem: Qs (unswizzled), KPs (K tile, later reused for P), Vs.
// K/V stored with XOR swizzle  elem[c][d] at c*64 + (d ^ (c&31)),
// P stored with                elem[r][c] at r*64 + (c ^ (r&31)).
// Exactly 48KB static shared.
// ---------------------------------------------------------------------------
__global__ __launch_bounds__(256) void attn_kernel() {
    __shared__ float Qs[64 * 64];
    __shared__ float KPs[64 * 64];
    __shared__ float Vs[64 * 64];

    const int bh = blockIdx.y;
    const int r0 = blockIdx.x * 64;
    const int tid = threadIdx.x;
    const int tx = tid & 15, ty = tid >> 4;

    const float* qb = g_q + (size_t)bh * N_TOK * DH;
    const float* kb = g_k + (size_t)bh * N_TOK * DH;
    const float* vb = g_v + (size_t)bh * N_TOK * DH;

    // Load Q tile (already scaled by 1/8)
#pragma unroll
    for (int p = 0; p < 4; p++) {
        const int row = p * 16 + (tid >> 4);
        const int c4 = (tid & 15) * 4;
        *(float4*)&Qs[row * 64 + c4] =
            *(const float4*)(qb + (size_t)(r0 + row) * DH + c4);
    }

    float m[4], l[4], Oa[4][4];
#pragma unroll
    for (int i = 0; i < 4; i++) {
        m[i] = -1e30f;
        l[i] = 0.f;
#pragma unroll
        for (int j = 0; j < 4; j++) Oa[i][j] = 0.f;
    }

    for (int t = 0; t < N_TOK / 64; t++) {
        __syncthreads();  // prev PV done (and Qs visible on t==0)

        // Load K & V tiles with swizzle
#pragma unroll
        for (int p = 0; p < 4; p++) {
            const int c = p * 16 + (tid >> 4);
            const int dq = (tid & 15) * 4;
            const int sw = c & 31;
            const size_t gofs = (size_t)(t * 64 + c) * DH + dq;
            float4 kv = *(const float4*)(kb + gofs);
            KPs[c * 64 + ((dq + 0) ^ sw)] = kv.x;
            KPs[c * 64 + ((dq + 1) ^ sw)] = kv.y;
            KPs[c * 64 + ((dq + 2) ^ sw)] = kv.z;
            KPs[c * 64 + ((dq + 3) ^ sw)] = kv.w;
            float4 vv = *(const float4*)(vb + gofs);
            Vs[c * 64 + ((dq + 0) ^ sw)] = vv.x;
            Vs[c * 64 + ((dq + 1) ^ sw)] = vv.y;
            Vs[c * 64 + ((dq + 2) ^ sw)] = vv.z;
            Vs[c * 64 + ((dq + 3) ^ sw)] = vv.w;
        }
        __syncthreads();

        // S = Q @ K^T  (scale already folded into Q)
        float acc[4][4];
#pragma unroll
        for (int i = 0; i < 4; i++)
#pragma unroll
            for (int j = 0; j < 4; j++) acc[i][j] = 0.f;

        int cbase[4], cswz[4];
#pragma unroll
        for (int j = 0; j < 4; j++) {
            const int c = tx * 4 + j;
            cbase[j] = c * 64;
            cswz[j] = c & 31;
        }
#pragma unroll 8
        for (int d = 0; d < 64; d++) {
            float rq[4], rk[4];
#pragma unroll
            for (int i = 0; i < 4; i++) rq[i] = Qs[(ty * 4 + i) * 64 + d];
#pragma unroll
            for (int j = 0; j < 4; j++) rk[j] = KPs[cbase[j] + (d ^ cswz[j])];
#pragma unroll
            for (int i = 0; i < 4; i++)
#pragma unroll
                for (int j = 0; j < 4; j++) acc[i][j] += rq[i] * rk[j];
        }

        // Online softmax (rows live in 16-lane groups: lanes sharing ty)
#pragma unroll
        for (int i = 0; i < 4; i++) {
            float mt = acc[i][0];
#pragma unroll
            for (int j = 1; j < 4; j++) mt = fmaxf(mt, acc[i][j]);
#pragma unroll
            for (int off = 1; off < 16; off <<= 1)
                mt = fmaxf(mt, __shfl_xor_sync(0xffffffffu, mt, off));
            const float mnew = fmaxf(m[i], mt);
            const float alpha = __expf(m[i] - mnew);
            float rs = 0.f;
#pragma unroll
            for (int j = 0; j < 4; j++) {
                const float pv = __expf(acc[i][j] - mnew);
                acc[i][j] = pv;
                rs += pv;
            }
#pragma unroll
            for (int off = 1; off < 16; off <<= 1)
                rs += __shfl_xor_sync(0xffffffffu, rs, off);
            l[i] = l[i] * alpha + rs;
            m[i] = mnew;
#pragma unroll
            for (int j = 0; j < 4; j++) Oa[i][j] *= alpha;
        }

        __syncthreads();  // everyone done reading K before overwriting with P
        // Stage P into KPs: P[r][c] at r*64 + (c ^ (r&31))
#pragma unroll
        for (int i = 0; i < 4; i++) {
            const int r = ty * 4 + i;
            const int rsw = r & 31;
#pragma unroll
            for (int j = 0; j < 4; j++)
                KPs[r * 64 + ((tx * 4 + j) ^ rsw)] = acc[i][j];
        }
        __syncthreads();

        // O += P @ V   (tx now indexes d)
#pragma unroll 8
        for (int c = 0; c < 64; c++) {
            float rp[4], rv[4];
            const int csw = c & 31;
#pragma unroll
            for (int i = 0; i < 4; i++) {
                const int r = ty * 4 + i;
                rp[i] = KPs[r * 64 + (c ^ (r & 31))];
            }
#pragma unroll
            for (int j = 0; j < 4; j++) rv[j] = Vs[c * 64 + ((tx * 4 + j) ^ csw)];
#pragma unroll
            for (int i = 0; i < 4; i++)
#pragma unroll
                for (int j = 0; j < 4; j++) Oa[i][j] += rp[i] * rv[j];
        }
    }

    // Normalize and write O[bh][n][d]
#pragma unroll
    for (int i = 0; i < 4; i++) {
        const float inv = 1.0f / l[i];
        float4 v = make_float4(Oa[i][0] * inv, Oa[i][1] * inv,
                               Oa[i][2] * inv, Oa[i][3] * inv);
        *(float4*)(g_o + ((size_t)bh * N_TOK + r0 + ty * 4 + i) * DH + tx * 4) = v;
    }
}

// ---------------------------------------------------------------------------
// Kernel 3: output projection + bias.
// out[b,c,n] = sum_i w_out[c,i] * O[b, i=(h*64+d), n] + b_out[c]
// where O is stored [bh][n][d]. Tile 64(c) x 64(n), K-chunks of 16
// (a 16-chunk never crosses an h boundary since 64 % 16 == 0).
// Thread map: tx -> n (coalesced stores), ty -> c.
// ---------------------------------------------------------------------------
__global__ __launch_bounds__(256) void outproj_kernel(const float* __restrict__ w,
                                                      const float* __restrict__ bias,
                                                      float* __restrict__ out) {
    __shared__ float As[16 * 65];    // [k][c] transposed, padded
    __shared__ float Bsn[64 * 17];   // [n][k], padded

    const int b  = blockIdx.z;
    const int c0 = blockIdx.x * 64;
    const int n0 = blockIdx.y * 64;
    const int tid = threadIdx.x;
    const int tx = tid & 15, ty = tid >> 4;

    const float* ob = g_o + (size_t)b * NH * N_TOK * DH;

    float acc[4][4];
#pragma unroll
    for (int i = 0; i < 4; i++)
#pragma unroll
        for (int j = 0; j < 4; j++) acc[i][j] = 0.f;

    for (int k0 = 0; k0 < INNER; k0 += 16) {
        const int h = k0 >> 6;
        const int dbase = k0 & 63;
        // W tile [64 c][16 k] -> As[k][c]
        {
            const int r = tid >> 2;
            const int c4 = (tid & 3) * 4;
            float4 wv = *(const float4*)(w + (size_t)(c0 + r) * INNER + k0 + c4);
            As[(c4 + 0) * 65 + r] = wv.x;
            As[(c4 + 1) * 65 + r] = wv.y;
            As[(c4 + 2) * 65 + r] = wv.z;
            As[(c4 + 3) * 65 + r] = wv.w;
        }
        // O tile: rows k (= d within head h), cols n; load float4 along d.
        {
            const int nidx = tid >> 2;         // 0..63
            const int kq = (tid & 3) * 4;      // 0..12
            float4 ov = *(const float4*)(ob + ((size_t)h * N_TOK + n0 + nidx) * DH +
                                         dbase + kq);
            Bsn[nidx * 17 + kq + 0] = ov.x;
            Bsn[nidx * 17 + kq + 1] = ov.y;
            Bsn[nidx * 17 + kq + 2] = ov.z;
            Bsn[nidx * 17 + kq + 3] = ov.w;
        }
        __syncthreads();

#pragma unroll
        for (int kk = 0; kk < 16; kk++) {
            float ra[4], rb[4];
#pragma unroll
            for (int i = 0; i < 4; i++) ra[i] = As[kk * 65 + ty * 4 + i];
#pragma unroll
            for (int j = 0; j < 4; j++) rb[j] = Bsn[(tx * 4 + j) * 17 + kk];
#pragma unroll
            for (int i = 0; i < 4; i++)
#pragma unroll
                for (int j = 0; j < 4; j++) acc[i][j] += ra[i] * rb[j];
        }
        __syncthreads();
    }

#pragma unroll
    for (int i = 0; i < 4; i++) {
        const int c = c0 + ty * 4 + i;
        const float bb = bias[c];
        float4 v = make_float4(acc[i][0] + bb, acc[i][1] + bb,
                               acc[i][2] + bb, acc[i][3] + bb);
        *(float4*)(out + ((size_t)b * CIN + c) * N_TOK + n0 + tx * 4) = v;
    }
}

// ---------------------------------------------------------------------------
// Launch: x, w_qkv, w_out, b_out (metadata order). Output fp32 [B,C,H,W].
// ---------------------------------------------------------------------------
extern "C" void kernel_launch(void* const* d_in, const int* in_sizes, int n_in,
                              void* d_out, int out_size) {
    const float* x     = (const float*)d_in[0];
    const float* w_qkv = (const float*)d_in[1];
    const float* w_out = (const float*)d_in[2];
    const float* b_out = (const float*)d_in[3];
    float* out = (float*)d_out;

    qkv_kernel<<<dim3(OQKV / 64, N_TOK / 64, NB), 256>>>(x, w_qkv);
    attn_kernel<<<dim3(N_TOK / 64, NB * NH), 256>>>();
    outproj_kernel<<<dim3(CIN / 64, N_TOK / 64, NB), 256>>>(w_out, b_out, out);
}